// round 2
// baseline (speedup 1.0000x reference)
#include <cuda_runtime.h>

// Problem constants
#define B_    8
#define C_    512
#define N_    1024
#define HEADS 8
#define DH    64
#define GROUPS 32

// Scratch (allocation-free: device globals)
__device__ float g_h[(size_t)B_ * C_ * N_];        // groupnorm output  (16 MB)
__device__ float g_qkv[(size_t)B_ * 3 * C_ * N_];  // qkv               (48 MB)
__device__ float g_ao[(size_t)B_ * C_ * N_];       // attention output  (16 MB)

// ---------------------------------------------------------------------------
// GroupNorm: one block per (batch, group). 16 channels x 1024 = 16384 elems.
// ---------------------------------------------------------------------------
__global__ __launch_bounds__(256)
void gn_kernel(const float* __restrict__ x, const float* __restrict__ w,
               const float* __restrict__ bb) {
    int bg = blockIdx.x;
    int b = bg >> 5, g = bg & 31;
    const float4* xp = (const float4*)(x + ((size_t)b * C_ + g * 16) * N_);
    float4* hp = (float4*)(g_h + ((size_t)b * C_ + g * 16) * N_);

    float s = 0.f, s2 = 0.f;
    for (int idx = threadIdx.x; idx < 4096; idx += 256) {
        float4 v = xp[idx];
        s  += v.x + v.y + v.z + v.w;
        s2 += v.x * v.x + v.y * v.y + v.z * v.z + v.w * v.w;
    }
    // warp reduce
    #pragma unroll
    for (int off = 16; off; off >>= 1) {
        s  += __shfl_xor_sync(0xffffffffu, s, off);
        s2 += __shfl_xor_sync(0xffffffffu, s2, off);
    }
    __shared__ float sh[16];
    __shared__ float smu, srstd;
    int warp = threadIdx.x >> 5, lane = threadIdx.x & 31;
    if (lane == 0) { sh[warp] = s; sh[warp + 8] = s2; }
    __syncthreads();
    if (threadIdx.x == 0) {
        float ts = 0.f, ts2 = 0.f;
        #pragma unroll
        for (int i = 0; i < 8; i++) { ts += sh[i]; ts2 += sh[i + 8]; }
        float mu  = ts * (1.f / 16384.f);
        float var = ts2 * (1.f / 16384.f) - mu * mu;
        smu = mu;
        srstd = rsqrtf(var + 1e-5f);
    }
    __syncthreads();
    float mu = smu, rstd = srstd;

    for (int idx = threadIdx.x; idx < 4096; idx += 256) {
        int c = g * 16 + (idx >> 8);   // 256 float4 per channel
        float wc = w[c], bc = bb[c];
        float4 v = xp[idx];
        float4 o;
        o.x = (v.x - mu) * rstd * wc + bc;
        o.y = (v.y - mu) * rstd * wc + bc;
        o.z = (v.z - mu) * rstd * wc + bc;
        o.w = (v.w - mu) * rstd * wc + bc;
        hp[idx] = o;
    }
}

// ---------------------------------------------------------------------------
// SGEMM: Out[b,o,n] = sum_c W[o,c] * Bm[b,c,n] + bias[o]  (+ X residual)
// Tiles 128x128xK16, 256 threads, 8x8 microtile.
// ---------------------------------------------------------------------------
template <bool RES>
__global__ __launch_bounds__(256)
void gemm_kernel(const float* __restrict__ W, const float* __restrict__ bias,
                 const float* __restrict__ Bm, const float* __restrict__ X,
                 float* __restrict__ Out, int M, int K) {
    __shared__ float As[128][17];   // [o][k], padded
    __shared__ float Bs[16][128];   // [k][n]

    int b  = blockIdx.z;
    const float* Bp = Bm + (size_t)b * K * N_;
    int n0 = blockIdx.x * 128, o0 = blockIdx.y * 128;
    int tid = threadIdx.x, tx = tid & 15, ty = tid >> 4;

    float acc[8][8];
    #pragma unroll
    for (int r = 0; r < 8; r++)
        #pragma unroll
        for (int c = 0; c < 8; c++) acc[r][c] = 0.f;

    for (int k0 = 0; k0 < K; k0 += 16) {
        #pragma unroll
        for (int t = 0; t < 8; t++) {
            int idx = t * 256 + tid;
            int o = idx >> 4, kk = idx & 15;
            As[o][kk] = W[(size_t)(o0 + o) * K + (k0 + kk)];
            int n = idx & 127, kb = idx >> 7;
            Bs[kb][n] = Bp[(size_t)(k0 + kb) * N_ + (n0 + n)];
        }
        __syncthreads();
        #pragma unroll
        for (int kk = 0; kk < 16; kk++) {
            float ar[8], br[8];
            #pragma unroll
            for (int r = 0; r < 8; r++) ar[r] = As[ty * 8 + r][kk];
            float4 b0 = *(const float4*)&Bs[kk][tx * 8];
            float4 b1 = *(const float4*)&Bs[kk][tx * 8 + 4];
            br[0] = b0.x; br[1] = b0.y; br[2] = b0.z; br[3] = b0.w;
            br[4] = b1.x; br[5] = b1.y; br[6] = b1.z; br[7] = b1.w;
            #pragma unroll
            for (int r = 0; r < 8; r++)
                #pragma unroll
                for (int c = 0; c < 8; c++)
                    acc[r][c] = fmaf(ar[r], br[c], acc[r][c]);
        }
        __syncthreads();
    }

    #pragma unroll
    for (int r = 0; r < 8; r++) {
        int o = o0 + ty * 8 + r;
        float bi = bias[o];
        size_t row = (size_t)b * M * N_ + (size_t)o * N_ + n0 + tx * 8;
        float* orow = Out + row;
        #pragma unroll
        for (int c = 0; c < 8; c++) {
            float v = acc[r][c] + bi;
            if (RES) v += X[row + c];
            orow[c] = v;
        }
    }
}

// ---------------------------------------------------------------------------
// Flash attention (fp32): per (b,h) and 128-query tile.
// S[i,j] = sum_d q[d,i] k[d,j] * 0.125 ; online softmax ; O[i,d] += P V^T.
// ---------------------------------------------------------------------------
#define AT_BM 128
#define AT_BN 128
#define AT_SMEM ((64 * 128 + 64 * 128 + 64 * 129 + 128 * 129) * 4)

__global__ __launch_bounds__(256, 1)
void attn_kernel(const float* __restrict__ qkv, float* __restrict__ ao) {
    extern __shared__ float sm[];
    float* Qs = sm;                 // [64][128]
    float* Ks = Qs + 64 * 128;      // [64][128]
    float* Vs = Ks + 64 * 128;      // [64][129]  (padded)
    float* Ps = Vs + 64 * 129;      // [128][129] (padded)

    int bh = blockIdx.y;
    int b = bh >> 3, h = bh & 7;
    int i0 = blockIdx.x * AT_BM;
    const float* qb = qkv + (((size_t)b * 3 + 0) * HEADS + h) * DH * N_;
    const float* kb = qkv + (((size_t)b * 3 + 1) * HEADS + h) * DH * N_;
    const float* vb = qkv + (((size_t)b * 3 + 2) * HEADS + h) * DH * N_;

    int tid = threadIdx.x, tx = tid & 15, ty = tid >> 4;

    // load Q tile: Qs[d][i]
    for (int idx = tid; idx < 2048; idx += 256) {
        int e = idx * 4;
        int i = e & 127, d = e >> 7;
        *(float4*)(Qs + d * 128 + i) = *(const float4*)(qb + (size_t)d * N_ + i0 + i);
    }

    float m_i[8], l_i[8], o_acc[8][4];
    #pragma unroll
    for (int r = 0; r < 8; r++) {
        m_i[r] = -1e30f; l_i[r] = 0.f;
        #pragma unroll
        for (int c = 0; c < 4; c++) o_acc[r][c] = 0.f;
    }

    for (int j0 = 0; j0 < N_; j0 += AT_BN) {
        __syncthreads();   // previous PV-gemm done with Vs/Ps; Q load visible
        for (int idx = tid; idx < 2048; idx += 256) {
            int e = idx * 4;
            int j = e & 127, d = e >> 7;
            *(float4*)(Ks + d * 128 + j) = *(const float4*)(kb + (size_t)d * N_ + j0 + j);
            float4 v = *(const float4*)(vb + (size_t)d * N_ + j0 + j);
            Vs[d * 129 + j]     = v.x;
            Vs[d * 129 + j + 1] = v.y;
            Vs[d * 129 + j + 2] = v.z;
            Vs[d * 129 + j + 3] = v.w;
        }
        __syncthreads();

        // S = Q^T K
        float acc[8][8];
        #pragma unroll
        for (int r = 0; r < 8; r++)
            #pragma unroll
            for (int c = 0; c < 8; c++) acc[r][c] = 0.f;

        for (int d = 0; d < 64; d++) {
            float qr[8], kr[8];
            #pragma unroll
            for (int r = 0; r < 8; r++) qr[r] = Qs[d * 128 + ty * 8 + r];
            float4 k0 = *(const float4*)(Ks + d * 128 + tx * 8);
            float4 k1 = *(const float4*)(Ks + d * 128 + tx * 8 + 4);
            kr[0] = k0.x; kr[1] = k0.y; kr[2] = k0.z; kr[3] = k0.w;
            kr[4] = k1.x; kr[5] = k1.y; kr[6] = k1.z; kr[7] = k1.w;
            #pragma unroll
            for (int r = 0; r < 8; r++)
                #pragma unroll
                for (int c = 0; c < 8; c++)
                    acc[r][c] = fmaf(qr[r], kr[c], acc[r][c]);
        }

        // scaled online softmax (rows distributed over tx half-warp groups)
        #pragma unroll
        for (int r = 0; r < 8; r++) {
            float rowm = -1e30f;
            #pragma unroll
            for (int c = 0; c < 8; c++) {
                acc[r][c] *= 0.125f;
                rowm = fmaxf(rowm, acc[r][c]);
            }
            #pragma unroll
            for (int off = 8; off; off >>= 1)
                rowm = fmaxf(rowm, __shfl_xor_sync(0xffffffffu, rowm, off));
            float mnew = fmaxf(m_i[r], rowm);
            float corr = __expf(m_i[r] - mnew);
            m_i[r] = mnew;
            l_i[r] *= corr;
            #pragma unroll
            for (int c = 0; c < 4; c++) o_acc[r][c] *= corr;

            float rsum = 0.f;
            #pragma unroll
            for (int c = 0; c < 8; c++) {
                float p = __expf(acc[r][c] - mnew);
                acc[r][c] = p;
                rsum += p;
            }
            #pragma unroll
            for (int off = 8; off; off >>= 1)
                rsum += __shfl_xor_sync(0xffffffffu, rsum, off);
            l_i[r] += rsum;

            #pragma unroll
            for (int c = 0; c < 8; c++)
                Ps[(ty * 8 + r) * 129 + tx * 8 + c] = acc[r][c];
        }
        __syncthreads();

        // O += P @ V^T :  o_acc[r][c] += sum_j Ps[i][j] * Vs[d][j]
        for (int j = 0; j < AT_BN; j++) {
            float pv[8], vv[4];
            #pragma unroll
            for (int r = 0; r < 8; r++) pv[r] = Ps[(ty * 8 + r) * 129 + j];
            #pragma unroll
            for (int c = 0; c < 4; c++) vv[c] = Vs[(tx * 4 + c) * 129 + j];
            #pragma unroll
            for (int r = 0; r < 8; r++)
                #pragma unroll
                for (int c = 0; c < 4; c++)
                    o_acc[r][c] = fmaf(pv[r], vv[c], o_acc[r][c]);
        }
    }

    // normalize, transpose through Ps, write coalesced
    __syncthreads();
    #pragma unroll
    for (int r = 0; r < 8; r++) {
        float inv = 1.f / l_i[r];
        #pragma unroll
        for (int c = 0; c < 4; c++)
            Ps[(ty * 8 + r) * 129 + (tx * 4 + c)] = o_acc[r][c] * inv;
    }
    __syncthreads();
    float* aob = ao + ((size_t)(b * HEADS + h) * DH) * N_;
    for (int idx = tid; idx < 64 * 128; idx += 256) {
        int i = idx & 127, d = idx >> 7;
        aob[(size_t)d * N_ + i0 + i] = Ps[i * 129 + d];
    }
}

// ---------------------------------------------------------------------------
extern "C" void kernel_launch(void* const* d_in, const int* in_sizes, int n_in,
                              void* d_out, int out_size) {
    const float* x      = (const float*)d_in[0];
    const float* gn_w   = (const float*)d_in[1];
    const float* gn_b   = (const float*)d_in[2];
    const float* qkv_w  = (const float*)d_in[3];
    const float* qkv_b  = (const float*)d_in[4];
    const float* proj_w = (const float*)d_in[5];
    const float* proj_b = (const float*)d_in[6];
    float* out = (float*)d_out;

    float *hbuf, *qkvbuf, *aobuf;
    cudaGetSymbolAddress((void**)&hbuf, g_h);
    cudaGetSymbolAddress((void**)&qkvbuf, g_qkv);
    cudaGetSymbolAddress((void**)&aobuf, g_ao);

    cudaFuncSetAttribute(attn_kernel, cudaFuncAttributeMaxDynamicSharedMemorySize, AT_SMEM);

    // 1) GroupNorm
    gn_kernel<<<B_ * GROUPS, 256>>>(x, gn_w, gn_b);
    // 2) QKV GEMM: [1536x512] x [512x1024] per batch
    gemm_kernel<false><<<dim3(8, 12, B_), 256>>>(qkv_w, qkv_b, hbuf, nullptr, qkvbuf, 1536, 512);
    // 3) Flash attention per (b,h) x query tile
    attn_kernel<<<dim3(N_ / AT_BM, B_ * HEADS), 256, AT_SMEM>>>(qkvbuf, aobuf);
    // 4) Proj GEMM + bias + residual
    gemm_kernel<true><<<dim3(8, 4, B_), 256>>>(proj_w, proj_b, aobuf, x, out, 512, 512);
}

// round 5
// speedup vs baseline: 1.6012x; 1.6012x over previous
#include <cuda_runtime.h>
#include <cstdint>

// Problem constants
#define B_    8
#define C_    512
#define N_    1024
#define HEADS 8
#define DH    64
#define GROUPS 32

// Scratch (allocation-free: device globals)
__device__ float g_h[(size_t)B_ * C_ * N_];        // groupnorm output  (16 MB)
__device__ float g_qkv[(size_t)B_ * 3 * C_ * N_];  // qkv               (48 MB)
__device__ float g_ao[(size_t)B_ * C_ * N_];       // attention output  (16 MB)

// ---------------------------------------------------------------------------
// tf32 helpers (plain sm_80+ PTX — safe for the sm_103 compile target)
// ---------------------------------------------------------------------------
__device__ __forceinline__ float to_tf32(float x) {
    float r;
    asm("cvt.rna.tf32.f32 %0, %1;" : "=f"(r) : "f"(x));
    return r;
}
__device__ __forceinline__ void mma_tf32(float* c, const uint32_t* a, const uint32_t* b) {
    asm("mma.sync.aligned.m16n8k8.row.col.f32.tf32.tf32.f32 "
        "{%0,%1,%2,%3}, {%4,%5,%6,%7}, {%8,%9}, {%0,%1,%2,%3};"
        : "+f"(c[0]), "+f"(c[1]), "+f"(c[2]), "+f"(c[3])
        : "r"(a[0]), "r"(a[1]), "r"(a[2]), "r"(a[3]), "r"(b[0]), "r"(b[1]));
}

// ---------------------------------------------------------------------------
// GroupNorm: one block per (batch, group). 16 channels x 1024 = 16384 elems.
// ---------------------------------------------------------------------------
__global__ __launch_bounds__(256)
void gn_kernel(const float* __restrict__ x, const float* __restrict__ w,
               const float* __restrict__ bb) {
    int bg = blockIdx.x;
    int b = bg >> 5, g = bg & 31;
    const float4* xp = (const float4*)(x + ((size_t)b * C_ + g * 16) * N_);
    float4* hp = (float4*)(g_h + ((size_t)b * C_ + g * 16) * N_);

    float s = 0.f, s2 = 0.f;
    for (int idx = threadIdx.x; idx < 4096; idx += 256) {
        float4 v = xp[idx];
        s  += v.x + v.y + v.z + v.w;
        s2 += v.x * v.x + v.y * v.y + v.z * v.z + v.w * v.w;
    }
    #pragma unroll
    for (int off = 16; off; off >>= 1) {
        s  += __shfl_xor_sync(0xffffffffu, s, off);
        s2 += __shfl_xor_sync(0xffffffffu, s2, off);
    }
    __shared__ float sh[16];
    __shared__ float smu, srstd;
    int warp = threadIdx.x >> 5, lane = threadIdx.x & 31;
    if (lane == 0) { sh[warp] = s; sh[warp + 8] = s2; }
    __syncthreads();
    if (threadIdx.x == 0) {
        float ts = 0.f, ts2 = 0.f;
        #pragma unroll
        for (int i = 0; i < 8; i++) { ts += sh[i]; ts2 += sh[i + 8]; }
        float mu  = ts * (1.f / 16384.f);
        float var = ts2 * (1.f / 16384.f) - mu * mu;
        smu = mu;
        srstd = rsqrtf(var + 1e-5f);
    }
    __syncthreads();
    float mu = smu, rstd = srstd;

    for (int idx = threadIdx.x; idx < 4096; idx += 256) {
        int c = g * 16 + (idx >> 8);
        float wc = w[c], bc = bb[c];
        float4 v = xp[idx];
        float4 o;
        o.x = (v.x - mu) * rstd * wc + bc;
        o.y = (v.y - mu) * rstd * wc + bc;
        o.z = (v.z - mu) * rstd * wc + bc;
        o.w = (v.w - mu) * rstd * wc + bc;
        hp[idx] = o;
    }
}

// ---------------------------------------------------------------------------
// tf32 mma.sync GEMM: Out[b,o,n] = sum_c W[o,c]*Bm[b,c,n] + bias[o] (+X res)
// CTA tile 128x128, 8 warps (2x4), warp tile 64x32, K-tile 32, m16n8k8.
// smem pitches: As pitch 36 -> A-frag bank (4r+c)%32 conflict-free;
//               Bs pitch 136 -> B-frag bank (8k+n)%32 conflict-free.
// ---------------------------------------------------------------------------
#define A_PITCH 36
#define B_PITCH 136

template <bool RES>
__global__ __launch_bounds__(256, 2)
void tc_gemm(const float* __restrict__ W, const float* __restrict__ bias,
             const float* __restrict__ Bm, const float* __restrict__ X,
             float* __restrict__ Out, int M) {
    __shared__ float As[128 * A_PITCH];   // 18.4 KB  [o][c]
    __shared__ float Bs[32 * B_PITCH];    // 17.4 KB  [c][n]

    const int K = 512;
    int tid = threadIdx.x;
    int wid = tid >> 5, lane = tid & 31;
    int g = lane >> 2, tg = lane & 3;       // fragment group / thread-in-group
    int warpM = wid >> 2, warpN = wid & 3;  // 2 x 4 warp grid
    int wmRow = warpM * 64, wnCol = warpN * 32;

    int b = blockIdx.z;
    int n0 = blockIdx.x * 128, o0 = blockIdx.y * 128;
    const float* Bp = Bm + (size_t)b * K * N_;

    float acc[4][4][4];
    #pragma unroll
    for (int mf = 0; mf < 4; mf++)
        #pragma unroll
        for (int nf = 0; nf < 4; nf++)
            #pragma unroll
            for (int i = 0; i < 4; i++) acc[mf][nf][i] = 0.f;

    for (int t = 0; t < 16; t++) {
        int k0 = t * 32;
        // --- load A tile (W[o0..o0+127][k0..k0+31]), convert to tf32 ---
        #pragma unroll
        for (int it = 0; it < 4; it++) {
            int idx = it * 256 + tid;
            int o = idx >> 3, k4 = idx & 7;
            float4 v = *(const float4*)(W + (size_t)(o0 + o) * K + k0 + k4 * 4);
            v.x = to_tf32(v.x); v.y = to_tf32(v.y);
            v.z = to_tf32(v.z); v.w = to_tf32(v.w);
            *(float4*)(As + o * A_PITCH + k4 * 4) = v;
        }
        // --- load B tile (Bm[k0..k0+31][n0..n0+127]), convert to tf32 ---
        #pragma unroll
        for (int it = 0; it < 4; it++) {
            int idx = it * 256 + tid;
            int c = idx >> 5, n4 = idx & 31;
            float4 v = *(const float4*)(Bp + (size_t)(k0 + c) * N_ + n0 + n4 * 4);
            v.x = to_tf32(v.x); v.y = to_tf32(v.y);
            v.z = to_tf32(v.z); v.w = to_tf32(v.w);
            *(float4*)(Bs + c * B_PITCH + n4 * 4) = v;
        }
        __syncthreads();

        #pragma unroll
        for (int kk = 0; kk < 32; kk += 8) {
            uint32_t a[4][4], bfr[4][2];
            #pragma unroll
            for (int mf = 0; mf < 4; mf++) {
                int r0 = wmRow + mf * 16 + g;
                const uint32_t* p0 = (const uint32_t*)(As + r0 * A_PITCH + kk + tg);
                const uint32_t* p1 = (const uint32_t*)(As + (r0 + 8) * A_PITCH + kk + tg);
                a[mf][0] = p0[0];
                a[mf][1] = p1[0];
                a[mf][2] = p0[4 / 1];   // col + 4
                a[mf][3] = p1[4 / 1];
            }
            #pragma unroll
            for (int nf = 0; nf < 4; nf++) {
                int col = wnCol + nf * 8 + g;
                bfr[nf][0] = *(const uint32_t*)(Bs + (kk + tg) * B_PITCH + col);
                bfr[nf][1] = *(const uint32_t*)(Bs + (kk + 4 + tg) * B_PITCH + col);
            }
            #pragma unroll
            for (int mf = 0; mf < 4; mf++)
                #pragma unroll
                for (int nf = 0; nf < 4; nf++)
                    mma_tf32(acc[mf][nf], a[mf], bfr[nf]);
        }
        __syncthreads();
    }

    // --- epilogue: direct fragment stores (float2), bias (+ residual) ---
    #pragma unroll
    for (int mf = 0; mf < 4; mf++) {
        int r0 = o0 + wmRow + mf * 16 + g;
        float bi0 = bias[r0], bi1 = bias[r0 + 8];
        size_t base0 = (size_t)b * M * N_ + (size_t)r0 * N_ + n0;
        size_t base1 = base0 + 8 * (size_t)N_;
        #pragma unroll
        for (int nf = 0; nf < 4; nf++) {
            int col = wnCol + nf * 8 + tg * 2;
            float2 v0 = make_float2(acc[mf][nf][0] + bi0, acc[mf][nf][1] + bi0);
            float2 v1 = make_float2(acc[mf][nf][2] + bi1, acc[mf][nf][3] + bi1);
            if (RES) {
                float2 x0 = *(const float2*)(X + base0 + col);
                float2 x1 = *(const float2*)(X + base1 + col);
                v0.x += x0.x; v0.y += x0.y;
                v1.x += x1.x; v1.y += x1.y;
            }
            *(float2*)(Out + base0 + col) = v0;
            *(float2*)(Out + base1 + col) = v1;
        }
    }
}

// ---------------------------------------------------------------------------
// Flash attention (fp32): per (b,h) and 128-query tile. (unchanged, proven)
// ---------------------------------------------------------------------------
#define AT_BM 128
#define AT_BN 128
#define AT_SMEM ((64 * 128 + 64 * 128 + 64 * 129 + 128 * 129) * 4)

__global__ __launch_bounds__(256, 1)
void attn_kernel(const float* __restrict__ qkv, float* __restrict__ ao) {
    extern __shared__ float sm[];
    float* Qs = sm;
    float* Ks = Qs + 64 * 128;
    float* Vs = Ks + 64 * 128;
    float* Ps = Vs + 64 * 129;

    int bh = blockIdx.y;
    int b = bh >> 3, h = bh & 7;
    int i0 = blockIdx.x * AT_BM;
    const float* qb = qkv + (((size_t)b * 3 + 0) * HEADS + h) * DH * N_;
    const float* kb = qkv + (((size_t)b * 3 + 1) * HEADS + h) * DH * N_;
    const float* vb = qkv + (((size_t)b * 3 + 2) * HEADS + h) * DH * N_;

    int tid = threadIdx.x, tx = tid & 15, ty = tid >> 4;

    for (int idx = tid; idx < 2048; idx += 256) {
        int e = idx * 4;
        int i = e & 127, d = e >> 7;
        *(float4*)(Qs + d * 128 + i) = *(const float4*)(qb + (size_t)d * N_ + i0 + i);
    }

    float m_i[8], l_i[8], o_acc[8][4];
    #pragma unroll
    for (int r = 0; r < 8; r++) {
        m_i[r] = -1e30f; l_i[r] = 0.f;
        #pragma unroll
        for (int c = 0; c < 4; c++) o_acc[r][c] = 0.f;
    }

    for (int j0 = 0; j0 < N_; j0 += AT_BN) {
        __syncthreads();
        for (int idx = tid; idx < 2048; idx += 256) {
            int e = idx * 4;
            int j = e & 127, d = e >> 7;
            *(float4*)(Ks + d * 128 + j) = *(const float4*)(kb + (size_t)d * N_ + j0 + j);
            float4 v = *(const float4*)(vb + (size_t)d * N_ + j0 + j);
            Vs[d * 129 + j]     = v.x;
            Vs[d * 129 + j + 1] = v.y;
            Vs[d * 129 + j + 2] = v.z;
            Vs[d * 129 + j + 3] = v.w;
        }
        __syncthreads();

        float acc[8][8];
        #pragma unroll
        for (int r = 0; r < 8; r++)
            #pragma unroll
            for (int c = 0; c < 8; c++) acc[r][c] = 0.f;

        for (int d = 0; d < 64; d++) {
            float qr[8], kr[8];
            #pragma unroll
            for (int r = 0; r < 8; r++) qr[r] = Qs[d * 128 + ty * 8 + r];
            float4 k0 = *(const float4*)(Ks + d * 128 + tx * 8);
            float4 k1 = *(const float4*)(Ks + d * 128 + tx * 8 + 4);
            kr[0] = k0.x; kr[1] = k0.y; kr[2] = k0.z; kr[3] = k0.w;
            kr[4] = k1.x; kr[5] = k1.y; kr[6] = k1.z; kr[7] = k1.w;
            #pragma unroll
            for (int r = 0; r < 8; r++)
                #pragma unroll
                for (int c = 0; c < 8; c++)
                    acc[r][c] = fmaf(qr[r], kr[c], acc[r][c]);
        }

        #pragma unroll
        for (int r = 0; r < 8; r++) {
            float rowm = -1e30f;
            #pragma unroll
            for (int c = 0; c < 8; c++) {
                acc[r][c] *= 0.125f;
                rowm = fmaxf(rowm, acc[r][c]);
            }
            #pragma unroll
            for (int off = 8; off; off >>= 1)
                rowm = fmaxf(rowm, __shfl_xor_sync(0xffffffffu, rowm, off));
            float mnew = fmaxf(m_i[r], rowm);
            float corr = __expf(m_i[r] - mnew);
            m_i[r] = mnew;
            l_i[r] *= corr;
            #pragma unroll
            for (int c = 0; c < 4; c++) o_acc[r][c] *= corr;

            float rsum = 0.f;
            #pragma unroll
            for (int c = 0; c < 8; c++) {
                float p = __expf(acc[r][c] - mnew);
                acc[r][c] = p;
                rsum += p;
            }
            #pragma unroll
            for (int off = 8; off; off >>= 1)
                rsum += __shfl_xor_sync(0xffffffffu, rsum, off);
            l_i[r] += rsum;

            #pragma unroll
            for (int c = 0; c < 8; c++)
                Ps[(ty * 8 + r) * 129 + tx * 8 + c] = acc[r][c];
        }
        __syncthreads();

        for (int j = 0; j < AT_BN; j++) {
            float pv[8], vv[4];
            #pragma unroll
            for (int r = 0; r < 8; r++) pv[r] = Ps[(ty * 8 + r) * 129 + j];
            #pragma unroll
            for (int c = 0; c < 4; c++) vv[c] = Vs[(tx * 4 + c) * 129 + j];
            #pragma unroll
            for (int r = 0; r < 8; r++)
                #pragma unroll
                for (int c = 0; c < 4; c++)
                    o_acc[r][c] = fmaf(pv[r], vv[c], o_acc[r][c]);
        }
    }

    __syncthreads();
    #pragma unroll
    for (int r = 0; r < 8; r++) {
        float inv = 1.f / l_i[r];
        #pragma unroll
        for (int c = 0; c < 4; c++)
            Ps[(ty * 8 + r) * 129 + (tx * 4 + c)] = o_acc[r][c] * inv;
    }
    __syncthreads();
    float* aob = ao + ((size_t)(b * HEADS + h) * DH) * N_;
    for (int idx = tid; idx < 64 * 128; idx += 256) {
        int i = idx & 127, d = idx >> 7;
        aob[(size_t)d * N_ + i0 + i] = Ps[i * 129 + d];
    }
}

// ---------------------------------------------------------------------------
extern "C" void kernel_launch(void* const* d_in, const int* in_sizes, int n_in,
                              void* d_out, int out_size) {
    const float* x      = (const float*)d_in[0];
    const float* gn_w   = (const float*)d_in[1];
    const float* gn_b   = (const float*)d_in[2];
    const float* qkv_w  = (const float*)d_in[3];
    const float* qkv_b  = (const float*)d_in[4];
    const float* proj_w = (const float*)d_in[5];
    const float* proj_b = (const float*)d_in[6];
    float* out = (float*)d_out;

    float *hbuf, *qkvbuf, *aobuf;
    cudaGetSymbolAddress((void**)&hbuf, g_h);
    cudaGetSymbolAddress((void**)&qkvbuf, g_qkv);
    cudaGetSymbolAddress((void**)&aobuf, g_ao);

    cudaFuncSetAttribute(attn_kernel, cudaFuncAttributeMaxDynamicSharedMemorySize, AT_SMEM);

    // 1) GroupNorm
    gn_kernel<<<B_ * GROUPS, 256>>>(x, gn_w, gn_b);
    // 2) QKV GEMM (tf32 mma.sync): [1536x512] x [512x1024] per batch
    tc_gemm<false><<<dim3(8, 12, B_), 256>>>(qkv_w, qkv_b, hbuf, nullptr, qkvbuf, 1536);
    // 3) Flash attention per (b,h) x query tile (fp32)
    attn_kernel<<<dim3(N_ / AT_BM, B_ * HEADS), 256, AT_SMEM>>>(qkvbuf, aobuf);
    // 4) Proj GEMM + bias + residual (tf32 mma.sync)
    tc_gemm<true><<<dim3(8, 4, B_), 256>>>(proj_w, proj_b, aobuf, x, out, 512);
}

// round 6
// speedup vs baseline: 3.2258x; 2.0146x over previous
#include <cuda_runtime.h>
#include <cstdint>

// Problem constants
#define B_    8
#define C_    512
#define N_    1024
#define HEADS 8
#define DH    64
#define GROUPS 32

// Scratch (allocation-free: device globals)
__device__ float g_h[(size_t)B_ * C_ * N_];        // groupnorm output  (16 MB)
__device__ float g_qkv[(size_t)B_ * 3 * C_ * N_];  // qkv               (48 MB)
__device__ float g_ao[(size_t)B_ * C_ * N_];       // attention output  (16 MB)

// ---------------------------------------------------------------------------
// tf32 helpers (plain sm_80+ PTX — safe for the sm_103 compile target)
// ---------------------------------------------------------------------------
__device__ __forceinline__ float to_tf32(float x) {
    float r;
    asm("cvt.rna.tf32.f32 %0, %1;" : "=f"(r) : "f"(x));
    return r;
}
__device__ __forceinline__ void mma_tf32(float* c, const uint32_t* a, const uint32_t* b) {
    asm("mma.sync.aligned.m16n8k8.row.col.f32.tf32.tf32.f32 "
        "{%0,%1,%2,%3}, {%4,%5,%6,%7}, {%8,%9}, {%0,%1,%2,%3};"
        : "+f"(c[0]), "+f"(c[1]), "+f"(c[2]), "+f"(c[3])
        : "r"(a[0]), "r"(a[1]), "r"(a[2]), "r"(a[3]), "r"(b[0]), "r"(b[1]));
}

// ---------------------------------------------------------------------------
// GroupNorm: one block per (batch, group). 16 channels x 1024 = 16384 elems.
// ---------------------------------------------------------------------------
__global__ __launch_bounds__(256)
void gn_kernel(const float* __restrict__ x, const float* __restrict__ w,
               const float* __restrict__ bb) {
    int bg = blockIdx.x;
    int b = bg >> 5, g = bg & 31;
    const float4* xp = (const float4*)(x + ((size_t)b * C_ + g * 16) * N_);
    float4* hp = (float4*)(g_h + ((size_t)b * C_ + g * 16) * N_);

    float s = 0.f, s2 = 0.f;
    for (int idx = threadIdx.x; idx < 4096; idx += 256) {
        float4 v = xp[idx];
        s  += v.x + v.y + v.z + v.w;
        s2 += v.x * v.x + v.y * v.y + v.z * v.z + v.w * v.w;
    }
    #pragma unroll
    for (int off = 16; off; off >>= 1) {
        s  += __shfl_xor_sync(0xffffffffu, s, off);
        s2 += __shfl_xor_sync(0xffffffffu, s2, off);
    }
    __shared__ float sh[16];
    __shared__ float smu, srstd;
    int warp = threadIdx.x >> 5, lane = threadIdx.x & 31;
    if (lane == 0) { sh[warp] = s; sh[warp + 8] = s2; }
    __syncthreads();
    if (threadIdx.x == 0) {
        float ts = 0.f, ts2 = 0.f;
        #pragma unroll
        for (int i = 0; i < 8; i++) { ts += sh[i]; ts2 += sh[i + 8]; }
        float mu  = ts * (1.f / 16384.f);
        float var = ts2 * (1.f / 16384.f) - mu * mu;
        smu = mu;
        srstd = rsqrtf(var + 1e-5f);
    }
    __syncthreads();
    float mu = smu, rstd = srstd;

    for (int idx = threadIdx.x; idx < 4096; idx += 256) {
        int c = g * 16 + (idx >> 8);
        float wc = w[c], bc = bb[c];
        float4 v = xp[idx];
        float4 o;
        o.x = (v.x - mu) * rstd * wc + bc;
        o.y = (v.y - mu) * rstd * wc + bc;
        o.z = (v.z - mu) * rstd * wc + bc;
        o.w = (v.w - mu) * rstd * wc + bc;
        hp[idx] = o;
    }
}

// ---------------------------------------------------------------------------
// tf32 mma.sync GEMM (unchanged, proven): Out = W*Bm + bias (+X residual)
// ---------------------------------------------------------------------------
#define A_PITCH 36
#define B_PITCH 136

template <bool RES>
__global__ __launch_bounds__(256, 2)
void tc_gemm(const float* __restrict__ W, const float* __restrict__ bias,
             const float* __restrict__ Bm, const float* __restrict__ X,
             float* __restrict__ Out, int M) {
    __shared__ float As[128 * A_PITCH];
    __shared__ float Bs[32 * B_PITCH];

    const int K = 512;
    int tid = threadIdx.x;
    int wid = tid >> 5, lane = tid & 31;
    int g = lane >> 2, tg = lane & 3;
    int warpM = wid >> 2, warpN = wid & 3;
    int wmRow = warpM * 64, wnCol = warpN * 32;

    int b = blockIdx.z;
    int n0 = blockIdx.x * 128, o0 = blockIdx.y * 128;
    const float* Bp = Bm + (size_t)b * K * N_;

    float acc[4][4][4];
    #pragma unroll
    for (int mf = 0; mf < 4; mf++)
        #pragma unroll
        for (int nf = 0; nf < 4; nf++)
            #pragma unroll
            for (int i = 0; i < 4; i++) acc[mf][nf][i] = 0.f;

    for (int t = 0; t < 16; t++) {
        int k0 = t * 32;
        #pragma unroll
        for (int it = 0; it < 4; it++) {
            int idx = it * 256 + tid;
            int o = idx >> 3, k4 = idx & 7;
            float4 v = *(const float4*)(W + (size_t)(o0 + o) * K + k0 + k4 * 4);
            v.x = to_tf32(v.x); v.y = to_tf32(v.y);
            v.z = to_tf32(v.z); v.w = to_tf32(v.w);
            *(float4*)(As + o * A_PITCH + k4 * 4) = v;
        }
        #pragma unroll
        for (int it = 0; it < 4; it++) {
            int idx = it * 256 + tid;
            int c = idx >> 5, n4 = idx & 31;
            float4 v = *(const float4*)(Bp + (size_t)(k0 + c) * N_ + n0 + n4 * 4);
            v.x = to_tf32(v.x); v.y = to_tf32(v.y);
            v.z = to_tf32(v.z); v.w = to_tf32(v.w);
            *(float4*)(Bs + c * B_PITCH + n4 * 4) = v;
        }
        __syncthreads();

        #pragma unroll
        for (int kk = 0; kk < 32; kk += 8) {
            uint32_t a[4][4], bfr[4][2];
            #pragma unroll
            for (int mf = 0; mf < 4; mf++) {
                int r0 = wmRow + mf * 16 + g;
                const uint32_t* p0 = (const uint32_t*)(As + r0 * A_PITCH + kk + tg);
                const uint32_t* p1 = (const uint32_t*)(As + (r0 + 8) * A_PITCH + kk + tg);
                a[mf][0] = p0[0];
                a[mf][1] = p1[0];
                a[mf][2] = p0[4];
                a[mf][3] = p1[4];
            }
            #pragma unroll
            for (int nf = 0; nf < 4; nf++) {
                int col = wnCol + nf * 8 + g;
                bfr[nf][0] = *(const uint32_t*)(Bs + (kk + tg) * B_PITCH + col);
                bfr[nf][1] = *(const uint32_t*)(Bs + (kk + 4 + tg) * B_PITCH + col);
            }
            #pragma unroll
            for (int mf = 0; mf < 4; mf++)
                #pragma unroll
                for (int nf = 0; nf < 4; nf++)
                    mma_tf32(acc[mf][nf], a[mf], bfr[nf]);
        }
        __syncthreads();
    }

    #pragma unroll
    for (int mf = 0; mf < 4; mf++) {
        int r0 = o0 + wmRow + mf * 16 + g;
        float bi0 = bias[r0], bi1 = bias[r0 + 8];
        size_t base0 = (size_t)b * M * N_ + (size_t)r0 * N_ + n0;
        size_t base1 = base0 + 8 * (size_t)N_;
        #pragma unroll
        for (int nf = 0; nf < 4; nf++) {
            int col = wnCol + nf * 8 + tg * 2;
            float2 v0 = make_float2(acc[mf][nf][0] + bi0, acc[mf][nf][1] + bi0);
            float2 v1 = make_float2(acc[mf][nf][2] + bi1, acc[mf][nf][3] + bi1);
            if (RES) {
                float2 x0 = *(const float2*)(X + base0 + col);
                float2 x1 = *(const float2*)(X + base1 + col);
                v0.x += x0.x; v0.y += x0.y;
                v1.x += x1.x; v1.y += x1.y;
            }
            *(float2*)(Out + base0 + col) = v0;
            *(float2*)(Out + base1 + col) = v1;
        }
    }
}

// ---------------------------------------------------------------------------
// tf32 mma.sync flash attention.
// CTA = one (b,h) x 128-query tile, 8 warps, warp tile 16(i) x 128(j).
// S = Q^T K from d-major smem (no transpose needed: per-lane scalar LDS).
// Online softmax fully in-warp; P via warp-private smem strip; O += P V^T.
// Pitch 132 => all fragment accesses bank-conflict-free: (4*tg+g)%32 distinct.
// ---------------------------------------------------------------------------
#define AP 132
#define ATC_SMEM ((3 * 64 * AP + 128 * AP) * 4)   // 168,960 B

__global__ __launch_bounds__(256, 1)
void attn_tc(const float* __restrict__ qkv, float* __restrict__ ao) {
    extern __shared__ float sm[];
    float* Qs = sm;               // [64][AP]  (pre-scaled by 0.125, tf32)
    float* Ks = Qs + 64 * AP;     // [64][AP]
    float* Vs = Ks + 64 * AP;     // [64][AP]
    float* Ps = Vs + 64 * AP;     // [128][AP], warp w owns rows w*16..w*16+15

    int bh = blockIdx.y;
    int b = bh >> 3, h = bh & 7;
    int i0 = blockIdx.x * 128;
    const float* qb = qkv + (((size_t)b * 3 + 0) * HEADS + h) * DH * N_;
    const float* kb = qkv + (((size_t)b * 3 + 1) * HEADS + h) * DH * N_;
    const float* vb = qkv + (((size_t)b * 3 + 2) * HEADS + h) * DH * N_;

    int tid = threadIdx.x;
    int wid = tid >> 5, lane = tid & 31;
    int g = lane >> 2, tg = lane & 3;
    int r0 = wid * 16;
    float* Psw = Ps + r0 * AP;

    // load Q tile (scaled by 1/8, tf32)
    #pragma unroll
    for (int it = 0; it < 8; it++) {
        int idx = it * 256 + tid;
        int i4 = idx & 31, d = idx >> 5;
        float4 v = *(const float4*)(qb + (size_t)d * N_ + i0 + i4 * 4);
        v.x = to_tf32(v.x * 0.125f); v.y = to_tf32(v.y * 0.125f);
        v.z = to_tf32(v.z * 0.125f); v.w = to_tf32(v.w * 0.125f);
        *(float4*)(Qs + d * AP + i4 * 4) = v;
    }

    float m0 = -1e30f, m1 = -1e30f, l0 = 0.f, l1 = 0.f;
    float o_acc[8][4];
    #pragma unroll
    for (int nf = 0; nf < 8; nf++)
        #pragma unroll
        for (int i = 0; i < 4; i++) o_acc[nf][i] = 0.f;

    for (int j0 = 0; j0 < N_; j0 += 128) {
        __syncthreads();   // Vs free (prev O-mma done), Qs visible (iter 0)
        #pragma unroll
        for (int it = 0; it < 8; it++) {
            int idx = it * 256 + tid;
            int j4 = idx & 31, d = idx >> 5;
            float4 kv = *(const float4*)(kb + (size_t)d * N_ + j0 + j4 * 4);
            kv.x = to_tf32(kv.x); kv.y = to_tf32(kv.y);
            kv.z = to_tf32(kv.z); kv.w = to_tf32(kv.w);
            *(float4*)(Ks + d * AP + j4 * 4) = kv;
            float4 vv = *(const float4*)(vb + (size_t)d * N_ + j0 + j4 * 4);
            vv.x = to_tf32(vv.x); vv.y = to_tf32(vv.y);
            vv.z = to_tf32(vv.z); vv.w = to_tf32(vv.w);
            *(float4*)(Vs + d * AP + j4 * 4) = vv;
        }
        __syncthreads();

        // S = Q^T K  (warp rows r0..r0+15, all 128 j)
        float acc[16][4];
        #pragma unroll
        for (int nf = 0; nf < 16; nf++)
            #pragma unroll
            for (int i = 0; i < 4; i++) acc[nf][i] = 0.f;

        #pragma unroll
        for (int kk = 0; kk < 64; kk += 8) {
            uint32_t a[4];
            const uint32_t* q0 = (const uint32_t*)(Qs + (kk + tg) * AP + r0 + g);
            const uint32_t* q1 = (const uint32_t*)(Qs + (kk + tg + 4) * AP + r0 + g);
            a[0] = q0[0]; a[1] = q0[8]; a[2] = q1[0]; a[3] = q1[8];
            #pragma unroll
            for (int nf = 0; nf < 16; nf++) {
                uint32_t bf[2];
                bf[0] = *(const uint32_t*)(Ks + (kk + tg) * AP + nf * 8 + g);
                bf[1] = *(const uint32_t*)(Ks + (kk + tg + 4) * AP + nf * 8 + g);
                mma_tf32(acc[nf], a, bf);
            }
        }

        // online softmax (rows r0+g and r0+g+8; reduce over tg group)
        float rm0 = -1e30f, rm1 = -1e30f;
        #pragma unroll
        for (int nf = 0; nf < 16; nf++) {
            rm0 = fmaxf(rm0, fmaxf(acc[nf][0], acc[nf][1]));
            rm1 = fmaxf(rm1, fmaxf(acc[nf][2], acc[nf][3]));
        }
        rm0 = fmaxf(rm0, __shfl_xor_sync(0xffffffffu, rm0, 1));
        rm0 = fmaxf(rm0, __shfl_xor_sync(0xffffffffu, rm0, 2));
        rm1 = fmaxf(rm1, __shfl_xor_sync(0xffffffffu, rm1, 1));
        rm1 = fmaxf(rm1, __shfl_xor_sync(0xffffffffu, rm1, 2));
        float mn0 = fmaxf(m0, rm0), mn1 = fmaxf(m1, rm1);
        float c0 = __expf(m0 - mn0), c1 = __expf(m1 - mn1);
        l0 *= c0; l1 *= c1;
        #pragma unroll
        for (int nf = 0; nf < 8; nf++) {
            o_acc[nf][0] *= c0; o_acc[nf][1] *= c0;
            o_acc[nf][2] *= c1; o_acc[nf][3] *= c1;
        }
        float s0 = 0.f, s1 = 0.f;
        #pragma unroll
        for (int nf = 0; nf < 16; nf++) {
            float p0 = __expf(acc[nf][0] - mn0);
            float p1 = __expf(acc[nf][1] - mn0);
            float p2 = __expf(acc[nf][2] - mn1);
            float p3 = __expf(acc[nf][3] - mn1);
            s0 += p0 + p1; s1 += p2 + p3;
            Psw[g * AP + nf * 8 + tg * 2]           = to_tf32(p0);
            Psw[g * AP + nf * 8 + tg * 2 + 1]       = to_tf32(p1);
            Psw[(g + 8) * AP + nf * 8 + tg * 2]     = to_tf32(p2);
            Psw[(g + 8) * AP + nf * 8 + tg * 2 + 1] = to_tf32(p3);
        }
        s0 += __shfl_xor_sync(0xffffffffu, s0, 1);
        s0 += __shfl_xor_sync(0xffffffffu, s0, 2);
        s1 += __shfl_xor_sync(0xffffffffu, s1, 1);
        s1 += __shfl_xor_sync(0xffffffffu, s1, 2);
        l0 += s0; l1 += s1; m0 = mn0; m1 = mn1;
        __syncwarp();

        // O += P @ V^T
        #pragma unroll
        for (int kk = 0; kk < 128; kk += 8) {
            uint32_t a[4];
            a[0] = *(const uint32_t*)(Psw + g * AP + kk + tg);
            a[1] = *(const uint32_t*)(Psw + (g + 8) * AP + kk + tg);
            a[2] = *(const uint32_t*)(Psw + g * AP + kk + tg + 4);
            a[3] = *(const uint32_t*)(Psw + (g + 8) * AP + kk + tg + 4);
            #pragma unroll
            for (int nf = 0; nf < 8; nf++) {
                uint32_t bf[2];
                bf[0] = *(const uint32_t*)(Vs + (nf * 8 + g) * AP + kk + tg);
                bf[1] = *(const uint32_t*)(Vs + (nf * 8 + g) * AP + kk + tg + 4);
                mma_tf32(o_acc[nf], a, bf);
            }
        }
        __syncwarp();   // Psw reads done before next iteration's stores
    }

    // epilogue: normalize, transpose via warp strip, coalesced [d][i] store
    float inv0 = 1.f / l0, inv1 = 1.f / l1;
    #pragma unroll
    for (int nf = 0; nf < 8; nf++) {
        Psw[g * AP + nf * 8 + tg * 2]           = o_acc[nf][0] * inv0;
        Psw[g * AP + nf * 8 + tg * 2 + 1]       = o_acc[nf][1] * inv0;
        Psw[(g + 8) * AP + nf * 8 + tg * 2]     = o_acc[nf][2] * inv1;
        Psw[(g + 8) * AP + nf * 8 + tg * 2 + 1] = o_acc[nf][3] * inv1;
    }
    __syncwarp();
    float* aob = ao + ((size_t)(b * HEADS + h) * DH) * N_;
    #pragma unroll
    for (int it = 0; it < 32; it++) {
        int idx = it * 32 + lane;
        int iloc = idx & 15, d = idx >> 4;
        aob[(size_t)d * N_ + i0 + r0 + iloc] = Psw[iloc * AP + d];
    }
}

// ---------------------------------------------------------------------------
extern "C" void kernel_launch(void* const* d_in, const int* in_sizes, int n_in,
                              void* d_out, int out_size) {
    const float* x      = (const float*)d_in[0];
    const float* gn_w   = (const float*)d_in[1];
    const float* gn_b   = (const float*)d_in[2];
    const float* qkv_w  = (const float*)d_in[3];
    const float* qkv_b  = (const float*)d_in[4];
    const float* proj_w = (const float*)d_in[5];
    const float* proj_b = (const float*)d_in[6];
    float* out = (float*)d_out;

    float *hbuf, *qkvbuf, *aobuf;
    cudaGetSymbolAddress((void**)&hbuf, g_h);
    cudaGetSymbolAddress((void**)&qkvbuf, g_qkv);
    cudaGetSymbolAddress((void**)&aobuf, g_ao);

    cudaFuncSetAttribute(attn_tc, cudaFuncAttributeMaxDynamicSharedMemorySize, ATC_SMEM);

    // 1) GroupNorm
    gn_kernel<<<B_ * GROUPS, 256>>>(x, gn_w, gn_b);
    // 2) QKV GEMM (tf32 mma.sync)
    tc_gemm<false><<<dim3(8, 12, B_), 256>>>(qkv_w, qkv_b, hbuf, nullptr, qkvbuf, 1536);
    // 3) Flash attention (tf32 mma.sync)
    attn_tc<<<dim3(8, B_ * HEADS), 256, ATC_SMEM>>>(qkvbuf, aobuf);
    // 4) Proj GEMM + bias + residual (tf32 mma.sync)
    tc_gemm<true><<<dim3(8, 4, B_), 256>>>(proj_w, proj_b, aobuf, x, out, 512);
}

// round 7
// speedup vs baseline: 3.3759x; 1.0465x over previous
#include <cuda_runtime.h>
#include <cstdint>

// Problem constants
#define B_    8
#define C_    512
#define N_    1024
#define HEADS 8
#define DH    64
#define GROUPS 32

// Scratch (allocation-free: device globals)
__device__ float g_h[(size_t)B_ * C_ * N_];        // groupnorm output  (16 MB)
__device__ float g_qkv[(size_t)B_ * 3 * C_ * N_];  // qkv               (48 MB)
__device__ float g_ao[(size_t)B_ * C_ * N_];       // attention output  (16 MB)

// ---------------------------------------------------------------------------
// helpers (plain sm_80+ PTX — safe for the sm_103 compile target)
// mma.sync tf32 reads the high 19 bits of the b32 register: raw fp32 operands
// are consumed with truncation rounding — no explicit cvt needed.
// ---------------------------------------------------------------------------
__device__ __forceinline__ void mma_tf32(float* c, const uint32_t* a, const uint32_t* b) {
    asm("mma.sync.aligned.m16n8k8.row.col.f32.tf32.tf32.f32 "
        "{%0,%1,%2,%3}, {%4,%5,%6,%7}, {%8,%9}, {%0,%1,%2,%3};"
        : "+f"(c[0]), "+f"(c[1]), "+f"(c[2]), "+f"(c[3])
        : "r"(a[0]), "r"(a[1]), "r"(a[2]), "r"(a[3]), "r"(b[0]), "r"(b[1]));
}
__device__ __forceinline__ uint32_t smem_u32(const void* p) {
    uint32_t a;
    asm("{ .reg .u64 t; cvta.to.shared.u64 t, %1; cvt.u32.u64 %0, t; }"
        : "=r"(a) : "l"(p));
    return a;
}
__device__ __forceinline__ void cp16(uint32_t dst, const void* src) {
    asm volatile("cp.async.cg.shared.global [%0], [%1], 16;" :: "r"(dst), "l"(src));
}
#define CP_COMMIT() asm volatile("cp.async.commit_group;" ::: "memory")
#define CP_WAIT(n)  asm volatile("cp.async.wait_group %0;" :: "n"(n) : "memory")

// ---------------------------------------------------------------------------
// GroupNorm: one block per (batch, group). 16 channels x 1024 = 16384 elems.
// ---------------------------------------------------------------------------
__global__ __launch_bounds__(256)
void gn_kernel(const float* __restrict__ x, const float* __restrict__ w,
               const float* __restrict__ bb) {
    int bg = blockIdx.x;
    int b = bg >> 5, g = bg & 31;
    const float4* xp = (const float4*)(x + ((size_t)b * C_ + g * 16) * N_);
    float4* hp = (float4*)(g_h + ((size_t)b * C_ + g * 16) * N_);

    float s = 0.f, s2 = 0.f;
    for (int idx = threadIdx.x; idx < 4096; idx += 256) {
        float4 v = xp[idx];
        s  += v.x + v.y + v.z + v.w;
        s2 += v.x * v.x + v.y * v.y + v.z * v.z + v.w * v.w;
    }
    #pragma unroll
    for (int off = 16; off; off >>= 1) {
        s  += __shfl_xor_sync(0xffffffffu, s, off);
        s2 += __shfl_xor_sync(0xffffffffu, s2, off);
    }
    __shared__ float sh[16];
    __shared__ float smu, srstd;
    int warp = threadIdx.x >> 5, lane = threadIdx.x & 31;
    if (lane == 0) { sh[warp] = s; sh[warp + 8] = s2; }
    __syncthreads();
    if (threadIdx.x == 0) {
        float ts = 0.f, ts2 = 0.f;
        #pragma unroll
        for (int i = 0; i < 8; i++) { ts += sh[i]; ts2 += sh[i + 8]; }
        float mu  = ts * (1.f / 16384.f);
        float var = ts2 * (1.f / 16384.f) - mu * mu;
        smu = mu;
        srstd = rsqrtf(var + 1e-5f);
    }
    __syncthreads();
    float mu = smu, rstd = srstd;

    for (int idx = threadIdx.x; idx < 4096; idx += 256) {
        int c = g * 16 + (idx >> 8);
        float wc = w[c], bc = bb[c];
        float4 v = xp[idx];
        float4 o;
        o.x = (v.x - mu) * rstd * wc + bc;
        o.y = (v.y - mu) * rstd * wc + bc;
        o.z = (v.z - mu) * rstd * wc + bc;
        o.w = (v.w - mu) * rstd * wc + bc;
        hp[idx] = o;
    }
}

// ---------------------------------------------------------------------------
// tf32 mma.sync GEMM, cp.async 2-stage pipeline.
// CTA tile 128x128, 8 warps (2x4), warp tile 64x32, K-tile 32, m16n8k8.
// ---------------------------------------------------------------------------
#define A_PITCH 36
#define B_PITCH 136
#define STG_F   (128 * A_PITCH + 32 * B_PITCH)        // floats per stage: 8960
#define GM_SMEM (2 * STG_F * 4)                       // 71,680 B

template <bool RES>
__global__ __launch_bounds__(256)
void tc_gemm(const float* __restrict__ W, const float* __restrict__ bias,
             const float* __restrict__ Bm, const float* __restrict__ X,
             float* __restrict__ Out, int M) {
    extern __shared__ float smp[];

    const int K = 512;
    int tid = threadIdx.x;
    int wid = tid >> 5, lane = tid & 31;
    int g = lane >> 2, tg = lane & 3;
    int warpM = wid >> 2, warpN = wid & 3;
    int wmRow = warpM * 64, wnCol = warpN * 32;

    int b = blockIdx.z;
    int n0 = blockIdx.x * 128, o0 = blockIdx.y * 128;
    const float* Bp = Bm + (size_t)b * K * N_;

    // per-thread load coords (fixed across tiles)
    int aO[4], aK[4], bC[4], bN[4];
    #pragma unroll
    for (int it = 0; it < 4; it++) {
        int idx = it * 256 + tid;
        aO[it] = idx >> 3;  aK[it] = (idx & 7) * 4;
        bC[it] = idx >> 5;  bN[it] = (idx & 31) * 4;
    }
    uint32_t sbase = smem_u32(smp);

    // issue loads for tile t into stage s
    auto load_tile = [&](int t, int s) {
        int k0 = t * 32;
        uint32_t as = sbase + (uint32_t)(s * STG_F) * 4u;
        uint32_t bs = as + 128u * A_PITCH * 4u;
        #pragma unroll
        for (int it = 0; it < 4; it++)
            cp16(as + (uint32_t)(aO[it] * A_PITCH + aK[it]) * 4u,
                 W + (size_t)(o0 + aO[it]) * K + k0 + aK[it]);
        #pragma unroll
        for (int it = 0; it < 4; it++)
            cp16(bs + (uint32_t)(bC[it] * B_PITCH + bN[it]) * 4u,
                 Bp + (size_t)(k0 + bC[it]) * N_ + n0 + bN[it]);
        CP_COMMIT();
    };

    float acc[4][4][4];
    #pragma unroll
    for (int mf = 0; mf < 4; mf++)
        #pragma unroll
        for (int nf = 0; nf < 4; nf++)
            #pragma unroll
            for (int i = 0; i < 4; i++) acc[mf][nf][i] = 0.f;

    load_tile(0, 0);

    for (int t = 0; t < 16; t++) {
        int s = t & 1;
        if (t + 1 < 16) {
            load_tile(t + 1, s ^ 1);
            CP_WAIT(1);
        } else {
            CP_WAIT(0);
        }
        __syncthreads();

        const float* As = smp + s * STG_F;
        const float* Bs = As + 128 * A_PITCH;

        #pragma unroll
        for (int kk = 0; kk < 32; kk += 8) {
            uint32_t a[4][4], bfr[4][2];
            #pragma unroll
            for (int mf = 0; mf < 4; mf++) {
                int r0 = wmRow + mf * 16 + g;
                const uint32_t* p0 = (const uint32_t*)(As + r0 * A_PITCH + kk + tg);
                const uint32_t* p1 = (const uint32_t*)(As + (r0 + 8) * A_PITCH + kk + tg);
                a[mf][0] = p0[0];
                a[mf][1] = p1[0];
                a[mf][2] = p0[4];
                a[mf][3] = p1[4];
            }
            #pragma unroll
            for (int nf = 0; nf < 4; nf++) {
                int col = wnCol + nf * 8 + g;
                bfr[nf][0] = *(const uint32_t*)(Bs + (kk + tg) * B_PITCH + col);
                bfr[nf][1] = *(const uint32_t*)(Bs + (kk + 4 + tg) * B_PITCH + col);
            }
            #pragma unroll
            for (int mf = 0; mf < 4; mf++)
                #pragma unroll
                for (int nf = 0; nf < 4; nf++)
                    mma_tf32(acc[mf][nf], a[mf], bfr[nf]);
        }
        __syncthreads();   // done reading stage s before it is overwritten
    }

    #pragma unroll
    for (int mf = 0; mf < 4; mf++) {
        int r0 = o0 + wmRow + mf * 16 + g;
        float bi0 = bias[r0], bi1 = bias[r0 + 8];
        size_t base0 = (size_t)b * M * N_ + (size_t)r0 * N_ + n0;
        size_t base1 = base0 + 8 * (size_t)N_;
        #pragma unroll
        for (int nf = 0; nf < 4; nf++) {
            int col = wnCol + nf * 8 + tg * 2;
            float2 v0 = make_float2(acc[mf][nf][0] + bi0, acc[mf][nf][1] + bi0);
            float2 v1 = make_float2(acc[mf][nf][2] + bi1, acc[mf][nf][3] + bi1);
            if (RES) {
                float2 x0 = *(const float2*)(X + base0 + col);
                float2 x1 = *(const float2*)(X + base1 + col);
                v0.x += x0.x; v0.y += x0.y;
                v1.x += x1.x; v1.y += x1.y;
            }
            *(float2*)(Out + base0 + col) = v0;
            *(float2*)(Out + base1 + col) = v1;
        }
    }
}

// ---------------------------------------------------------------------------
// tf32 mma.sync flash attention (raw-fp32 operands; cvts removed).
// CTA = one (b,h) x 128-query tile, 8 warps, warp tile 16(i) x 128(j).
// ---------------------------------------------------------------------------
#define AP 132
#define ATC_SMEM ((3 * 64 * AP + 128 * AP) * 4)   // 168,960 B

__global__ __launch_bounds__(256, 1)
void attn_tc(const float* __restrict__ qkv, float* __restrict__ ao) {
    extern __shared__ float sm[];
    float* Qs = sm;               // [64][AP]  (pre-scaled by 0.125)
    float* Ks = Qs + 64 * AP;     // [64][AP]
    float* Vs = Ks + 64 * AP;     // [64][AP]
    float* Ps = Vs + 64 * AP;     // [128][AP], warp w owns rows w*16..w*16+15

    int bh = blockIdx.y;
    int b = bh >> 3, h = bh & 7;
    int i0 = blockIdx.x * 128;
    const float* qb = qkv + (((size_t)b * 3 + 0) * HEADS + h) * DH * N_;
    const float* kb = qkv + (((size_t)b * 3 + 1) * HEADS + h) * DH * N_;
    const float* vb = qkv + (((size_t)b * 3 + 2) * HEADS + h) * DH * N_;

    int tid = threadIdx.x;
    int wid = tid >> 5, lane = tid & 31;
    int g = lane >> 2, tg = lane & 3;
    int r0 = wid * 16;
    float* Psw = Ps + r0 * AP;

    // load Q tile (scaled by 1/8; raw fp32, mma truncates to tf32)
    #pragma unroll
    for (int it = 0; it < 8; it++) {
        int idx = it * 256 + tid;
        int i4 = idx & 31, d = idx >> 5;
        float4 v = *(const float4*)(qb + (size_t)d * N_ + i0 + i4 * 4);
        v.x *= 0.125f; v.y *= 0.125f; v.z *= 0.125f; v.w *= 0.125f;
        *(float4*)(Qs + d * AP + i4 * 4) = v;
    }

    float m0 = -1e30f, m1 = -1e30f, l0 = 0.f, l1 = 0.f;
    float o_acc[8][4];
    #pragma unroll
    for (int nf = 0; nf < 8; nf++)
        #pragma unroll
        for (int i = 0; i < 4; i++) o_acc[nf][i] = 0.f;

    for (int j0 = 0; j0 < N_; j0 += 128) {
        __syncthreads();
        #pragma unroll
        for (int it = 0; it < 8; it++) {
            int idx = it * 256 + tid;
            int j4 = idx & 31, d = idx >> 5;
            *(float4*)(Ks + d * AP + j4 * 4) =
                *(const float4*)(kb + (size_t)d * N_ + j0 + j4 * 4);
            *(float4*)(Vs + d * AP + j4 * 4) =
                *(const float4*)(vb + (size_t)d * N_ + j0 + j4 * 4);
        }
        __syncthreads();

        float acc[16][4];
        #pragma unroll
        for (int nf = 0; nf < 16; nf++)
            #pragma unroll
            for (int i = 0; i < 4; i++) acc[nf][i] = 0.f;

        #pragma unroll
        for (int kk = 0; kk < 64; kk += 8) {
            uint32_t a[4];
            const uint32_t* q0 = (const uint32_t*)(Qs + (kk + tg) * AP + r0 + g);
            const uint32_t* q1 = (const uint32_t*)(Qs + (kk + tg + 4) * AP + r0 + g);
            a[0] = q0[0]; a[1] = q0[8]; a[2] = q1[0]; a[3] = q1[8];
            #pragma unroll
            for (int nf = 0; nf < 16; nf++) {
                uint32_t bf[2];
                bf[0] = *(const uint32_t*)(Ks + (kk + tg) * AP + nf * 8 + g);
                bf[1] = *(const uint32_t*)(Ks + (kk + tg + 4) * AP + nf * 8 + g);
                mma_tf32(acc[nf], a, bf);
            }
        }

        float rm0 = -1e30f, rm1 = -1e30f;
        #pragma unroll
        for (int nf = 0; nf < 16; nf++) {
            rm0 = fmaxf(rm0, fmaxf(acc[nf][0], acc[nf][1]));
            rm1 = fmaxf(rm1, fmaxf(acc[nf][2], acc[nf][3]));
        }
        rm0 = fmaxf(rm0, __shfl_xor_sync(0xffffffffu, rm0, 1));
        rm0 = fmaxf(rm0, __shfl_xor_sync(0xffffffffu, rm0, 2));
        rm1 = fmaxf(rm1, __shfl_xor_sync(0xffffffffu, rm1, 1));
        rm1 = fmaxf(rm1, __shfl_xor_sync(0xffffffffu, rm1, 2));
        float mn0 = fmaxf(m0, rm0), mn1 = fmaxf(m1, rm1);
        float c0 = __expf(m0 - mn0), c1 = __expf(m1 - mn1);
        l0 *= c0; l1 *= c1;
        #pragma unroll
        for (int nf = 0; nf < 8; nf++) {
            o_acc[nf][0] *= c0; o_acc[nf][1] *= c0;
            o_acc[nf][2] *= c1; o_acc[nf][3] *= c1;
        }
        float s0 = 0.f, s1 = 0.f;
        #pragma unroll
        for (int nf = 0; nf < 16; nf++) {
            float p0 = __expf(acc[nf][0] - mn0);
            float p1 = __expf(acc[nf][1] - mn0);
            float p2 = __expf(acc[nf][2] - mn1);
            float p3 = __expf(acc[nf][3] - mn1);
            s0 += p0 + p1; s1 += p2 + p3;
            Psw[g * AP + nf * 8 + tg * 2]           = p0;
            Psw[g * AP + nf * 8 + tg * 2 + 1]       = p1;
            Psw[(g + 8) * AP + nf * 8 + tg * 2]     = p2;
            Psw[(g + 8) * AP + nf * 8 + tg * 2 + 1] = p3;
        }
        s0 += __shfl_xor_sync(0xffffffffu, s0, 1);
        s0 += __shfl_xor_sync(0xffffffffu, s0, 2);
        s1 += __shfl_xor_sync(0xffffffffu, s1, 1);
        s1 += __shfl_xor_sync(0xffffffffu, s1, 2);
        l0 += s0; l1 += s1; m0 = mn0; m1 = mn1;
        __syncwarp();

        #pragma unroll
        for (int kk = 0; kk < 128; kk += 8) {
            uint32_t a[4];
            a[0] = *(const uint32_t*)(Psw + g * AP + kk + tg);
            a[1] = *(const uint32_t*)(Psw + (g + 8) * AP + kk + tg);
            a[2] = *(const uint32_t*)(Psw + g * AP + kk + tg + 4);
            a[3] = *(const uint32_t*)(Psw + (g + 8) * AP + kk + tg + 4);
            #pragma unroll
            for (int nf = 0; nf < 8; nf++) {
                uint32_t bf[2];
                bf[0] = *(const uint32_t*)(Vs + (nf * 8 + g) * AP + kk + tg);
                bf[1] = *(const uint32_t*)(Vs + (nf * 8 + g) * AP + kk + tg + 4);
                mma_tf32(o_acc[nf], a, bf);
            }
        }
        __syncwarp();
    }

    float inv0 = 1.f / l0, inv1 = 1.f / l1;
    #pragma unroll
    for (int nf = 0; nf < 8; nf++) {
        Psw[g * AP + nf * 8 + tg * 2]           = o_acc[nf][0] * inv0;
        Psw[g * AP + nf * 8 + tg * 2 + 1]       = o_acc[nf][1] * inv0;
        Psw[(g + 8) * AP + nf * 8 + tg * 2]     = o_acc[nf][2] * inv1;
        Psw[(g + 8) * AP + nf * 8 + tg * 2 + 1] = o_acc[nf][3] * inv1;
    }
    __syncwarp();
    float* aob = ao + ((size_t)(b * HEADS + h) * DH) * N_;
    #pragma unroll
    for (int it = 0; it < 32; it++) {
        int idx = it * 32 + lane;
        int iloc = idx & 15, d = idx >> 4;
        aob[(size_t)d * N_ + i0 + r0 + iloc] = Psw[iloc * AP + d];
    }
}

// ---------------------------------------------------------------------------
extern "C" void kernel_launch(void* const* d_in, const int* in_sizes, int n_in,
                              void* d_out, int out_size) {
    const float* x      = (const float*)d_in[0];
    const float* gn_w   = (const float*)d_in[1];
    const float* gn_b   = (const float*)d_in[2];
    const float* qkv_w  = (const float*)d_in[3];
    const float* qkv_b  = (const float*)d_in[4];
    const float* proj_w = (const float*)d_in[5];
    const float* proj_b = (const float*)d_in[6];
    float* out = (float*)d_out;

    float *hbuf, *qkvbuf, *aobuf;
    cudaGetSymbolAddress((void**)&hbuf, g_h);
    cudaGetSymbolAddress((void**)&qkvbuf, g_qkv);
    cudaGetSymbolAddress((void**)&aobuf, g_ao);

    cudaFuncSetAttribute(attn_tc, cudaFuncAttributeMaxDynamicSharedMemorySize, ATC_SMEM);
    cudaFuncSetAttribute(tc_gemm<false>, cudaFuncAttributeMaxDynamicSharedMemorySize, GM_SMEM);
    cudaFuncSetAttribute(tc_gemm<true>,  cudaFuncAttributeMaxDynamicSharedMemorySize, GM_SMEM);

    // 1) GroupNorm
    gn_kernel<<<B_ * GROUPS, 256>>>(x, gn_w, gn_b);
    // 2) QKV GEMM (tf32 mma.sync, cp.async pipelined)
    tc_gemm<false><<<dim3(8, 12, B_), 256, GM_SMEM>>>(qkv_w, qkv_b, hbuf, nullptr, qkvbuf, 1536);
    // 3) Flash attention (tf32 mma.sync)
    attn_tc<<<dim3(8, B_ * HEADS), 256, ATC_SMEM>>>(qkvbuf, aobuf);
    // 4) Proj GEMM + bias + residual (tf32 mma.sync, cp.async pipelined)
    tc_gemm<true><<<dim3(8, 4, B_), 256, GM_SMEM>>>(proj_w, proj_b, aobuf, x, out, 512);
}

// round 9
// speedup vs baseline: 5.2427x; 1.5530x over previous
#include <cuda_runtime.h>
#include <cstdint>

// Problem constants
#define B_    8
#define C_    512
#define N_    1024
#define HEADS 8
#define DH    64
#define GROUPS 32

// Scratch (allocation-free: device globals). All bf16 pair-packed as u32 words.
__device__ uint32_t g_h[(size_t)B_ * 256 * 1024];     // GN out, word(c2,n)   (8 MB)
__device__ uint32_t g_qkvw[(size_t)B_ * 1536 * 512];  // qkv bf16 [row][n/2]  (25 MB)
__device__ uint32_t g_aow[(size_t)B_ * 256 * 1024];   // attn out word(c2,n)  (8 MB)
__device__ uint32_t g_wq[1536 * 256];                 // qkv_w bf16
__device__ uint32_t g_wp[512 * 256];                  // proj_w bf16

// ---------------------------------------------------------------------------
// helpers (plain sm_80+ PTX — safe for the sm_103 compile target)
// ---------------------------------------------------------------------------
__device__ __forceinline__ void mma_bf16(float* c, const uint32_t* a, const uint32_t* b) {
    asm("mma.sync.aligned.m16n8k16.row.col.f32.bf16.bf16.f32 "
        "{%0,%1,%2,%3}, {%4,%5,%6,%7}, {%8,%9}, {%0,%1,%2,%3};"
        : "+f"(c[0]), "+f"(c[1]), "+f"(c[2]), "+f"(c[3])
        : "r"(a[0]), "r"(a[1]), "r"(a[2]), "r"(a[3]), "r"(b[0]), "r"(b[1]));
}
__device__ __forceinline__ uint32_t bf2(float lo, float hi) {   // word: lo16=lo
    uint32_t w;
    asm("cvt.rn.satfinite.bf16x2.f32 %0, %1, %2;" : "=r"(w) : "f"(hi), "f"(lo));
    return w;
}
__device__ __forceinline__ uint32_t prmt(uint32_t a, uint32_t b, uint32_t s) {
    uint32_t d;
    asm("prmt.b32 %0, %1, %2, %3;" : "=r"(d) : "r"(a), "r"(b), "r"(s));
    return d;
}
__device__ __forceinline__ uint32_t smem_u32(const void* p) {
    uint32_t a;
    asm("{ .reg .u64 t; cvta.to.shared.u64 t, %1; cvt.u32.u64 %0, t; }"
        : "=r"(a) : "l"(p));
    return a;
}
__device__ __forceinline__ void cp16(uint32_t dst, const void* src) {
    asm volatile("cp.async.cg.shared.global [%0], [%1], 16;" :: "r"(dst), "l"(src));
}
#define CP_COMMIT() asm volatile("cp.async.commit_group;" ::: "memory")
#define CP_WAIT(n)  asm volatile("cp.async.wait_group %0;" :: "n"(n) : "memory")

// ---------------------------------------------------------------------------
// Weight conversion: fp32 row-major -> bf16 pair words (same layout)
// ---------------------------------------------------------------------------
__global__ __launch_bounds__(256)
void wconv(const float4* __restrict__ src, uint2* __restrict__ dst, int n4) {
    int i = blockIdx.x * 256 + threadIdx.x;
    if (i < n4) {
        float4 v = src[i];
        dst[i] = make_uint2(bf2(v.x, v.y), bf2(v.z, v.w));
    }
}

// ---------------------------------------------------------------------------
// GroupNorm -> bf16 word(c2, n) = (h[2c2,n], h[2c2+1,n])
// ---------------------------------------------------------------------------
__global__ __launch_bounds__(256)
void gn_kernel(const float* __restrict__ x, const float* __restrict__ w,
               const float* __restrict__ bb) {
    int bg = blockIdx.x;
    int b = bg >> 5, g = bg & 31;
    const float4* xp = (const float4*)(x + ((size_t)b * C_ + g * 16) * N_);

    float s = 0.f, s2 = 0.f;
    for (int idx = threadIdx.x; idx < 4096; idx += 256) {
        float4 v = xp[idx];
        s  += v.x + v.y + v.z + v.w;
        s2 += v.x * v.x + v.y * v.y + v.z * v.z + v.w * v.w;
    }
    #pragma unroll
    for (int off = 16; off; off >>= 1) {
        s  += __shfl_xor_sync(0xffffffffu, s, off);
        s2 += __shfl_xor_sync(0xffffffffu, s2, off);
    }
    __shared__ float sh[16];
    __shared__ float smu, srstd;
    int warp = threadIdx.x >> 5, lane = threadIdx.x & 31;
    if (lane == 0) { sh[warp] = s; sh[warp + 8] = s2; }
    __syncthreads();
    if (threadIdx.x == 0) {
        float ts = 0.f, ts2 = 0.f;
        #pragma unroll
        for (int i = 0; i < 8; i++) { ts += sh[i]; ts2 += sh[i + 8]; }
        float mu  = ts * (1.f / 16384.f);
        float var = ts2 * (1.f / 16384.f) - mu * mu;
        smu = mu;
        srstd = rsqrtf(var + 1e-5f);
    }
    __syncthreads();
    float mu = smu, rstd = srstd;

    uint32_t* hw = g_h + ((size_t)(b * 256 + g * 8)) * 1024;
    int tid = threadIdx.x;
    #pragma unroll
    for (int cc = 0; cc < 8; cc++) {
        int c = g * 16 + cc * 2;
        float s0 = w[c] * rstd,     t0 = bb[c]     - mu * s0;
        float s1 = w[c + 1] * rstd, t1 = bb[c + 1] - mu * s1;
        const float4* xa = (const float4*)(x + ((size_t)b * C_ + c) * N_);
        float4 va = xa[tid], vb = xa[256 + tid];
        uint4 wv;
        wv.x = bf2(va.x * s0 + t0, vb.x * s1 + t1);
        wv.y = bf2(va.y * s0 + t0, vb.y * s1 + t1);
        wv.z = bf2(va.z * s0 + t0, vb.z * s1 + t1);
        wv.w = bf2(va.w * s0 + t0, vb.w * s1 + t1);
        *(uint4*)(hw + cc * 1024 + tid * 4) = wv;
    }
}

// ---------------------------------------------------------------------------
// bf16 mma.sync GEMM, cp.async 2-stage pipeline.
// CTA 128x128, 8 warps (2x4), warp tile 64x32, K-tile 32 (=16 k2 words).
// A: bf16 words [M][256]; B: words [256][1024] per batch (k-pair rows).
// RES=false -> bf16 word output (qkv); RES=true -> fp32 + residual.
// ---------------------------------------------------------------------------
#define PA 20
#define PB 136
#define STG_W (128 * PA + 16 * PB)            // 4736 words per stage
#define GM_SMEM (2 * STG_W * 4)               // 37,888 B

template <bool RES>
__global__ __launch_bounds__(256)
void tc_gemm(const uint32_t* __restrict__ A, const float* __restrict__ bias,
             const uint32_t* __restrict__ Bw, const float* __restrict__ X,
             float* __restrict__ OutF, uint32_t* __restrict__ OutW, int M) {
    extern __shared__ uint32_t smp[];

    int tid = threadIdx.x;
    int wid = tid >> 5, lane = tid & 31;
    int g = lane >> 2, tg = lane & 3;
    int warpM = wid >> 2, warpN = wid & 3;
    int wmRow = warpM * 64, wnCol = warpN * 32;

    int b = blockIdx.z;
    int n0 = blockIdx.x * 128, o0 = blockIdx.y * 128;
    const uint32_t* Bp = Bw + (size_t)b * 256 * 1024;

    uint32_t sbase = smem_u32(smp);

    auto load_tile = [&](int t, int s) {
        uint32_t as = sbase + (uint32_t)(s * STG_W) * 4u;
        uint32_t bs = as + 128u * PA * 4u;
        #pragma unroll
        for (int it = 0; it < 2; it++) {
            int idx = it * 256 + tid;
            int o = idx >> 2, ch = idx & 3;
            cp16(as + (uint32_t)(o * PA + ch * 4) * 4u,
                 A + (size_t)(o0 + o) * 256 + t * 16 + ch * 4);
        }
        #pragma unroll
        for (int it = 0; it < 2; it++) {
            int idx = it * 256 + tid;
            int r = idx >> 5, ch = idx & 31;
            cp16(bs + (uint32_t)(r * PB + ch * 4) * 4u,
                 Bp + (size_t)(t * 16 + r) * 1024 + n0 + ch * 4);
        }
        CP_COMMIT();
    };

    float acc[4][4][4];
    #pragma unroll
    for (int mf = 0; mf < 4; mf++)
        #pragma unroll
        for (int nf = 0; nf < 4; nf++)
            #pragma unroll
            for (int i = 0; i < 4; i++) acc[mf][nf][i] = 0.f;

    load_tile(0, 0);

    for (int t = 0; t < 16; t++) {
        int s = t & 1;
        if (t + 1 < 16) { load_tile(t + 1, s ^ 1); CP_WAIT(1); }
        else           { CP_WAIT(0); }
        __syncthreads();

        const uint32_t* As = smp + s * STG_W;
        const uint32_t* Bs = As + 128 * PA;

        #pragma unroll
        for (int ks = 0; ks < 2; ks++) {
            uint32_t a[4][4], bfr[4][2];
            #pragma unroll
            for (int mf = 0; mf < 4; mf++) {
                int r = wmRow + mf * 16 + g;
                a[mf][0] = As[r * PA + ks * 8 + tg];
                a[mf][1] = As[(r + 8) * PA + ks * 8 + tg];
                a[mf][2] = As[r * PA + ks * 8 + tg + 4];
                a[mf][3] = As[(r + 8) * PA + ks * 8 + tg + 4];
            }
            #pragma unroll
            for (int nf = 0; nf < 4; nf++) {
                int col = wnCol + nf * 8 + g;
                bfr[nf][0] = Bs[(ks * 8 + tg) * PB + col];
                bfr[nf][1] = Bs[(ks * 8 + tg + 4) * PB + col];
            }
            #pragma unroll
            for (int mf = 0; mf < 4; mf++)
                #pragma unroll
                for (int nf = 0; nf < 4; nf++)
                    mma_bf16(acc[mf][nf], a[mf], bfr[nf]);
        }
        __syncthreads();
    }

    #pragma unroll
    for (int mf = 0; mf < 4; mf++) {
        int r = o0 + wmRow + mf * 16 + g;
        float bi0 = bias[r], bi1 = bias[r + 8];
        if (RES) {
            size_t base0 = (size_t)b * M * N_ + (size_t)r * N_ + n0;
            size_t base1 = base0 + 8 * (size_t)N_;
            #pragma unroll
            for (int nf = 0; nf < 4; nf++) {
                int col = wnCol + nf * 8 + tg * 2;
                float2 v0 = make_float2(acc[mf][nf][0] + bi0, acc[mf][nf][1] + bi0);
                float2 v1 = make_float2(acc[mf][nf][2] + bi1, acc[mf][nf][3] + bi1);
                float2 x0 = *(const float2*)(X + base0 + col);
                float2 x1 = *(const float2*)(X + base1 + col);
                v0.x += x0.x; v0.y += x0.y;
                v1.x += x1.x; v1.y += x1.y;
                *(float2*)(OutF + base0 + col) = v0;
                *(float2*)(OutF + base1 + col) = v1;
            }
        } else {
            size_t w0 = ((size_t)b * 1536 + r) * 512;
            size_t w1 = w0 + 8 * 512;
            #pragma unroll
            for (int nf = 0; nf < 4; nf++) {
                int wc = ((n0 + wnCol + nf * 8) >> 1) + tg;
                OutW[w0 + wc] = bf2(acc[mf][nf][0] + bi0, acc[mf][nf][1] + bi0);
                OutW[w1 + wc] = bf2(acc[mf][nf][2] + bi1, acc[mf][nf][3] + bi1);
            }
        }
    }
}

// ---------------------------------------------------------------------------
// bf16 mma.sync flash attention.
// CTA = (b,h) x 128-query tile, 8 warps, warp tile 16(i) x 128(j).
// Qs/Ks: word(d2,i) [32][136]; Vs: word(j2,d) [64][72]; Ps strip [128][68].
// 1/8 scale folded into exp2 constant.
// ---------------------------------------------------------------------------
#define PQ 136
#define PV 72
#define PP 68
#define QS_OFF 0
#define KS_OFF (32 * PQ)
#define VS_OFF (2 * 32 * PQ)
#define PS_OFF (2 * 32 * PQ + 64 * PV)
#define ATT_SMEM ((PS_OFF + 128 * PP) * 4)    // 88,064 B
#define K8 0.18033688011112042f               // 0.125 * log2(e)

__global__ __launch_bounds__(256, 2)
void attn_tc(const uint32_t* __restrict__ qkvw, uint32_t* __restrict__ aow) {
    extern __shared__ uint32_t smw[];
    uint32_t* Qs = smw + QS_OFF;
    uint32_t* Ks = smw + KS_OFF;
    uint32_t* Vs = smw + VS_OFF;
    uint32_t* Ps = smw + PS_OFF;

    int bh = blockIdx.y;
    int b = bh >> 3, h = bh & 7;
    int i0 = blockIdx.x * 128;
    const uint32_t* qb = qkvw + ((size_t)b * 1536 + h * 64) * 512;
    const uint32_t* kb = qb + (size_t)512 * 512;
    const uint32_t* vb = qb + (size_t)1024 * 512;

    int tid = threadIdx.x;
    int wid = tid >> 5, lane = tid & 31;
    int g = lane >> 2, tg = lane & 3;
    int r0 = wid * 16;
    uint32_t* Psw = Ps + r0 * PP;

    // load Q tile: word(d2, i) via prmt interleave of rows 2d2, 2d2+1
    #pragma unroll
    for (int it = 0; it < 2; it++) {
        int idx = it * 256 + tid;
        int d2 = idx >> 4, ch = idx & 15;
        uint4 a = *(const uint4*)(qb + (size_t)(2 * d2) * 512 + (i0 >> 1) + ch * 4);
        uint4 c = *(const uint4*)(qb + (size_t)(2 * d2 + 1) * 512 + (i0 >> 1) + ch * 4);
        *(uint4*)(Qs + d2 * PQ + ch * 8) = make_uint4(
            prmt(a.x, c.x, 0x5410), prmt(a.x, c.x, 0x7632),
            prmt(a.y, c.y, 0x5410), prmt(a.y, c.y, 0x7632));
        *(uint4*)(Qs + d2 * PQ + ch * 8 + 4) = make_uint4(
            prmt(a.z, c.z, 0x5410), prmt(a.z, c.z, 0x7632),
            prmt(a.w, c.w, 0x5410), prmt(a.w, c.w, 0x7632));
    }

    float m0 = -1e30f, m1 = -1e30f, l0 = 0.f, l1 = 0.f;
    float o_acc[8][4];
    #pragma unroll
    for (int nf = 0; nf < 8; nf++)
        #pragma unroll
        for (int i = 0; i < 4; i++) o_acc[nf][i] = 0.f;

    for (int j0 = 0; j0 < N_; j0 += 128) {
        __syncthreads();
        // K tile (interleaved like Q)
        #pragma unroll
        for (int it = 0; it < 2; it++) {
            int idx = it * 256 + tid;
            int d2 = idx >> 4, ch = idx & 15;
            uint4 a = *(const uint4*)(kb + (size_t)(2 * d2) * 512 + (j0 >> 1) + ch * 4);
            uint4 c = *(const uint4*)(kb + (size_t)(2 * d2 + 1) * 512 + (j0 >> 1) + ch * 4);
            *(uint4*)(Ks + d2 * PQ + ch * 8) = make_uint4(
                prmt(a.x, c.x, 0x5410), prmt(a.x, c.x, 0x7632),
                prmt(a.y, c.y, 0x5410), prmt(a.y, c.y, 0x7632));
            *(uint4*)(Ks + d2 * PQ + ch * 8 + 4) = make_uint4(
                prmt(a.z, c.z, 0x5410), prmt(a.z, c.z, 0x7632),
                prmt(a.w, c.w, 0x5410), prmt(a.w, c.w, 0x7632));
        }
        // V tile: word(j2, d) scatter (j-pairs are native in memory)
        #pragma unroll
        for (int it = 0; it < 4; it++) {
            int idx = it * 256 + tid;
            int d = idx >> 4, ch = idx & 15;
            uint4 v = *(const uint4*)(vb + (size_t)d * 512 + (j0 >> 1) + ch * 4);
            Vs[(ch * 4 + 0) * PV + d] = v.x;
            Vs[(ch * 4 + 1) * PV + d] = v.y;
            Vs[(ch * 4 + 2) * PV + d] = v.z;
            Vs[(ch * 4 + 3) * PV + d] = v.w;
        }
        __syncthreads();

        // S = Q^T K
        float acc[16][4];
        #pragma unroll
        for (int nf = 0; nf < 16; nf++)
            #pragma unroll
            for (int i = 0; i < 4; i++) acc[nf][i] = 0.f;

        #pragma unroll
        for (int kk = 0; kk < 32; kk += 8) {
            uint32_t a[4];
            a[0] = Qs[(kk + tg) * PQ + r0 + g];
            a[1] = Qs[(kk + tg) * PQ + r0 + g + 8];
            a[2] = Qs[(kk + tg + 4) * PQ + r0 + g];
            a[3] = Qs[(kk + tg + 4) * PQ + r0 + g + 8];
            #pragma unroll
            for (int nf = 0; nf < 16; nf++) {
                uint32_t bf[2];
                bf[0] = Ks[(kk + tg) * PQ + nf * 8 + g];
                bf[1] = Ks[(kk + tg + 4) * PQ + nf * 8 + g];
                mma_bf16(acc[nf], a, bf);
            }
        }

        // online softmax in raw units; 1/8 folded into exp2 constant
        float rm0 = -1e30f, rm1 = -1e30f;
        #pragma unroll
        for (int nf = 0; nf < 16; nf++) {
            rm0 = fmaxf(rm0, fmaxf(acc[nf][0], acc[nf][1]));
            rm1 = fmaxf(rm1, fmaxf(acc[nf][2], acc[nf][3]));
        }
        rm0 = fmaxf(rm0, __shfl_xor_sync(0xffffffffu, rm0, 1));
        rm0 = fmaxf(rm0, __shfl_xor_sync(0xffffffffu, rm0, 2));
        rm1 = fmaxf(rm1, __shfl_xor_sync(0xffffffffu, rm1, 1));
        rm1 = fmaxf(rm1, __shfl_xor_sync(0xffffffffu, rm1, 2));
        float mn0 = fmaxf(m0, rm0), mn1 = fmaxf(m1, rm1);
        float c0 = exp2f((m0 - mn0) * K8), c1 = exp2f((m1 - mn1) * K8);
        l0 *= c0; l1 *= c1;
        #pragma unroll
        for (int nf = 0; nf < 8; nf++) {
            o_acc[nf][0] *= c0; o_acc[nf][1] *= c0;
            o_acc[nf][2] *= c1; o_acc[nf][3] *= c1;
        }
        float s0 = 0.f, s1 = 0.f;
        #pragma unroll
        for (int nf = 0; nf < 16; nf++) {
            float p0 = exp2f((acc[nf][0] - mn0) * K8);
            float p1 = exp2f((acc[nf][1] - mn0) * K8);
            float p2 = exp2f((acc[nf][2] - mn1) * K8);
            float p3 = exp2f((acc[nf][3] - mn1) * K8);
            s0 += p0 + p1; s1 += p2 + p3;
            Psw[g * PP + nf * 4 + tg]       = bf2(p0, p1);
            Psw[(g + 8) * PP + nf * 4 + tg] = bf2(p2, p3);
        }
        s0 += __shfl_xor_sync(0xffffffffu, s0, 1);
        s0 += __shfl_xor_sync(0xffffffffu, s0, 2);
        s1 += __shfl_xor_sync(0xffffffffu, s1, 1);
        s1 += __shfl_xor_sync(0xffffffffu, s1, 2);
        l0 += s0; l1 += s1; m0 = mn0; m1 = mn1;
        __syncwarp();

        // O += P @ V^T
        #pragma unroll
        for (int kk = 0; kk < 64; kk += 8) {
            uint32_t a[4];
            a[0] = Psw[g * PP + kk + tg];
            a[1] = Psw[(g + 8) * PP + kk + tg];
            a[2] = Psw[g * PP + kk + tg + 4];
            a[3] = Psw[(g + 8) * PP + kk + tg + 4];
            #pragma unroll
            for (int nf = 0; nf < 8; nf++) {
                uint32_t bf[2];
                bf[0] = Vs[(kk + tg) * PV + nf * 8 + g];
                bf[1] = Vs[(kk + tg + 4) * PV + nf * 8 + g];
                mma_bf16(o_acc[nf], a, bf);
            }
        }
        __syncwarp();
    }

    // epilogue: normalize, pack d-pairs, transpose via strip (pitch 37)
    float inv0 = 1.f / l0, inv1 = 1.f / l1;
    #pragma unroll
    for (int nf = 0; nf < 8; nf++) {
        int d2 = nf * 4 + tg;
        Psw[g * 37 + d2]       = bf2(o_acc[nf][0] * inv0, o_acc[nf][1] * inv0);
        Psw[(g + 8) * 37 + d2] = bf2(o_acc[nf][2] * inv1, o_acc[nf][3] * inv1);
    }
    __syncwarp();
    uint32_t* aob = aow + ((size_t)(b * 256 + h * 32)) * 1024;
    #pragma unroll
    for (int it = 0; it < 16; it++) {
        int idx = it * 32 + lane;
        int iloc = idx & 15, d2 = idx >> 4;
        aob[(size_t)d2 * 1024 + i0 + r0 + iloc] = Psw[iloc * 37 + d2];
    }
}

// ---------------------------------------------------------------------------
extern "C" void kernel_launch(void* const* d_in, const int* in_sizes, int n_in,
                              void* d_out, int out_size) {
    const float* x      = (const float*)d_in[0];
    const float* gn_w   = (const float*)d_in[1];
    const float* gn_b   = (const float*)d_in[2];
    const float* qkv_w  = (const float*)d_in[3];
    const float* qkv_b  = (const float*)d_in[4];
    const float* proj_w = (const float*)d_in[5];
    const float* proj_b = (const float*)d_in[6];
    float* out = (float*)d_out;

    uint32_t *hbuf, *qkvbuf, *aobuf, *wq, *wp;
    cudaGetSymbolAddress((void**)&hbuf,   g_h);
    cudaGetSymbolAddress((void**)&qkvbuf, g_qkvw);
    cudaGetSymbolAddress((void**)&aobuf,  g_aow);
    cudaGetSymbolAddress((void**)&wq,     g_wq);
    cudaGetSymbolAddress((void**)&wp,     g_wp);

    cudaFuncSetAttribute(attn_tc, cudaFuncAttributeMaxDynamicSharedMemorySize, ATT_SMEM);

    // 0) weight conversion (fp32 -> bf16 words)
    wconv<<<768, 256>>>((const float4*)qkv_w, (uint2*)wq, 1536 * 128);
    wconv<<<256, 256>>>((const float4*)proj_w, (uint2*)wp, 512 * 128);
    // 1) GroupNorm -> bf16 pair words
    gn_kernel<<<B_ * GROUPS, 256>>>(x, gn_w, gn_b);
    // 2) QKV GEMM (bf16 mma.sync, cp.async) -> bf16 q/k/v
    tc_gemm<false><<<dim3(8, 12, B_), 256, GM_SMEM>>>(wq, qkv_b, hbuf, nullptr,
                                                      nullptr, qkvbuf, 1536);
    // 3) Flash attention (bf16 mma.sync) -> bf16 pair words
    attn_tc<<<dim3(8, B_ * HEADS), 256, ATT_SMEM>>>(qkvbuf, aobuf);
    // 4) Proj GEMM + bias + residual (bf16 mma.sync) -> fp32 out
    tc_gemm<true><<<dim3(8, 4, B_), 256, GM_SMEM>>>(wp, proj_b, aobuf, x,
                                                    out, nullptr, 512);
}